// round 1
// baseline (speedup 1.0000x reference)
#include <cuda_runtime.h>

#define NB 16
#define NF 6
#define NPIX 262144
#define NK 8
#define NITERS 12
#define BPB 32          // blocks per batch in pass kernels
#define SPLIT 8         // blocks per (b,f) in stats kernel
#define NSLOT 56        // NK*(NF+1) partial-sum slots

// Scratch (static __device__ — no allocations allowed)
__device__ float d_statpart[NB * NF * SPLIT * 2];
__device__ float d_mean[NB * NF];
__device__ float d_sinv[NB * NF];
__device__ float d_g[NB * NK * NF];   // folded centroid weights: 2*alpha*s_f*c_kf
__device__ float d_h[NB * NK];        // folded centroid bias
__device__ float d_part[NB * BPB * NSLOT];

__device__ __forceinline__ float ex2f(float x) {
    float y; asm("ex2.approx.ftz.f32 %0, %1;" : "=f"(y) : "f"(x)); return y;
}
__device__ __forceinline__ float rcpf(float x) {
    float y; asm("rcp.approx.ftz.f32 %0, %1;" : "=f"(y) : "f"(x)); return y;
}

// ---------------------------------------------------------------------------
// Per-(b,f) sum / sumsq partials over pixels
// ---------------------------------------------------------------------------
__global__ __launch_bounds__(256) void stats_kernel(const float* __restrict__ feat) {
    int bf = blockIdx.x >> 3;     // / SPLIT
    int part = blockIdx.x & 7;    // % SPLIT
    const float4* p = ((const float4*)feat) + (size_t)bf * (NPIX / 4);
    int t = threadIdx.x;
    float s = 0.f, q = 0.f;
    #pragma unroll 8
    for (int i = 0; i < 32; i++) {
        float4 v = p[part * 8192 + i * 256 + t];
        s += (v.x + v.y) + (v.z + v.w);
        q = fmaf(v.x, v.x, q); q = fmaf(v.y, v.y, q);
        q = fmaf(v.z, v.z, q); q = fmaf(v.w, v.w, q);
    }
    #pragma unroll
    for (int o = 16; o; o >>= 1) {
        s += __shfl_xor_sync(0xffffffffu, s, o);
        q += __shfl_xor_sync(0xffffffffu, q, o);
    }
    __shared__ float sm[16];
    if ((t & 31) == 0) { sm[t >> 5] = s; sm[8 + (t >> 5)] = q; }
    __syncthreads();
    if (t == 0) {
        float S = 0.f, Q = 0.f;
        #pragma unroll
        for (int i = 0; i < 8; i++) { S += sm[i]; Q += sm[8 + i]; }
        d_statpart[(bf * SPLIT + part) * 2 + 0] = S;
        d_statpart[(bf * SPLIT + part) * 2 + 1] = Q;
    }
}

// ---------------------------------------------------------------------------
// Finalize mean/invstd; gather initial centroids; fold into (g, h)
// logit_k(pixel) = sum_f u_f * g_kf + h_k   (softmax shift-invariance used to
// drop the per-pixel x2/T term; log2e folded so exp is a single MUFU ex2)
// ---------------------------------------------------------------------------
__global__ void init_kernel(const float* __restrict__ feat, const int* __restrict__ idx) {
    int t = threadIdx.x;  // 128 = NB*NK
    if (t < NB * NF) {
        float S = 0.f, Q = 0.f;
        for (int i = 0; i < SPLIT; i++) {
            S += d_statpart[(t * SPLIT + i) * 2 + 0];
            Q += d_statpart[(t * SPLIT + i) * 2 + 1];
        }
        float mean = S * (1.f / (float)NPIX);
        float var = (Q - (float)NPIX * mean * mean) * (1.f / (float)(NPIX - 1));
        var = fmaxf(var, 0.f);
        float sd = sqrtf(var);
        d_mean[t] = mean;
        d_sinv[t] = 1.f / fmaxf(sd, 1e-6f);
    }
    __syncthreads();
    int b = t >> 3;
    int n = idx[t];
    const float alpha = 1.4426950408889634f / 0.15f;  // log2(e)/TEMP
    float c2 = 0.f;
    float g[NF];
    #pragma unroll
    for (int f = 0; f < NF; f++) {
        float u = feat[(size_t)(b * NF + f) * NPIX + n];
        float c = (u - d_mean[b * NF + f]) * d_sinv[b * NF + f];
        c2 = fmaf(c, c, c2);
        g[f] = 2.f * alpha * d_sinv[b * NF + f] * c;
    }
    float h = -alpha * c2;
    #pragma unroll
    for (int f = 0; f < NF; f++) {
        h -= d_mean[b * NF + f] * g[f];
        d_g[t * NF + f] = g[f];
    }
    d_h[t] = h;
}

// ---------------------------------------------------------------------------
// Main accumulation pass: softmax assignment + accumulate (W, A) partials
// ---------------------------------------------------------------------------
__global__ __launch_bounds__(256, 1) void pass_acc_kernel(const float* __restrict__ feat) {
    int b = blockIdx.x >> 5;   // / BPB
    int blk = blockIdx.x & 31; // % BPB
    int t = threadIdx.x;

    float g[NK][NF], h[NK];
    #pragma unroll
    for (int k = 0; k < NK; k++) {
        h[k] = d_h[b * NK + k];
        #pragma unroll
        for (int f = 0; f < NF; f++) g[k][f] = d_g[(b * NK + k) * NF + f];
    }
    float aW[NK];
    float aA[NK][NF];
    #pragma unroll
    for (int k = 0; k < NK; k++) {
        aW[k] = 0.f;
        #pragma unroll
        for (int f = 0; f < NF; f++) aA[k][f] = 0.f;
    }

    const float* base = feat + (size_t)b * NF * NPIX;
    #pragma unroll
    for (int it = 0; it < 8; it++) {
        int n4 = blk * 256 + t + it * 8192;
        float4 u[NF];
        #pragma unroll
        for (int f = 0; f < NF; f++)
            u[f] = ((const float4*)(base + (size_t)f * NPIX))[n4];
        #pragma unroll
        for (int j = 0; j < 4; j++) {
            float x[NF];
            #pragma unroll
            for (int f = 0; f < NF; f++)
                x[f] = (j == 0) ? u[f].x : ((j == 1) ? u[f].y : ((j == 2) ? u[f].z : u[f].w));
            float l[NK];
            #pragma unroll
            for (int k = 0; k < NK; k++) {
                float a = h[k];
                #pragma unroll
                for (int f = 0; f < NF; f++) a = fmaf(x[f], g[k][f], a);
                l[k] = a;
            }
            float m = l[0];
            #pragma unroll
            for (int k = 1; k < NK; k++) m = fmaxf(m, l[k]);
            float p[NK]; float s = 0.f;
            #pragma unroll
            for (int k = 0; k < NK; k++) { p[k] = ex2f(l[k] - m); s += p[k]; }
            float r = rcpf(s);
            float xr[NF];
            #pragma unroll
            for (int f = 0; f < NF; f++) xr[f] = x[f] * r;
            #pragma unroll
            for (int k = 0; k < NK; k++) {
                aW[k] = fmaf(p[k], r, aW[k]);
                #pragma unroll
                for (int f = 0; f < NF; f++) aA[k][f] = fmaf(p[k], xr[f], aA[k][f]);
            }
        }
    }

    // Deterministic block reduction: warp shfl -> smem per-warp -> fixed-order sum
    __shared__ float sm[8][NSLOT];
    int w = t >> 5, lane = t & 31;
    #pragma unroll
    for (int k = 0; k < NK; k++) {
        #pragma unroll
        for (int f = 0; f < NF; f++) {
            float v = aA[k][f];
            #pragma unroll
            for (int o = 16; o; o >>= 1) v += __shfl_xor_sync(0xffffffffu, v, o);
            if (lane == 0) sm[w][k * NF + f] = v;
        }
        float v = aW[k];
        #pragma unroll
        for (int o = 16; o; o >>= 1) v += __shfl_xor_sync(0xffffffffu, v, o);
        if (lane == 0) sm[w][48 + k] = v;
    }
    __syncthreads();
    if (t < NSLOT) {
        float v = 0.f;
        #pragma unroll
        for (int i = 0; i < 8; i++) v += sm[i][t];
        d_part[(size_t)(b * BPB + blk) * NSLOT + t] = v;
    }
}

// ---------------------------------------------------------------------------
// Centroid update in raw-u space, refold into (g, h); fixed reduction order
// ---------------------------------------------------------------------------
__global__ void update_kernel() {
    int t = threadIdx.x;  // 128 = NB*NK
    int b = t >> 3, k = t & 7;
    float W = 0.f;
    float A[NF] = {0.f, 0.f, 0.f, 0.f, 0.f, 0.f};
    for (int blk = 0; blk < BPB; blk++) {
        const float* pp = d_part + (size_t)(b * BPB + blk) * NSLOT;
        W += pp[48 + k];
        #pragma unroll
        for (int f = 0; f < NF; f++) A[f] += pp[k * NF + f];
    }
    float Wc = fmaxf(W, 1e-6f);
    float rW = 1.f / Wc;
    const float alpha = 1.4426950408889634f / 0.15f;
    float c2 = 0.f;
    float g[NF];
    #pragma unroll
    for (int f = 0; f < NF; f++) {
        // C_kf = s_f * (A_f - m_f*W) / clip(W, EPS)   (matches reference exactly)
        float c = d_sinv[b * NF + f] * (A[f] - d_mean[b * NF + f] * W) * rW;
        c2 = fmaf(c, c, c2);
        g[f] = 2.f * alpha * d_sinv[b * NF + f] * c;
    }
    float h = -alpha * c2;
    #pragma unroll
    for (int f = 0; f < NF; f++) {
        h -= d_mean[b * NF + f] * g[f];
        d_g[t * NF + f] = g[f];
    }
    d_h[t] = h;
}

// ---------------------------------------------------------------------------
// Final pass: compute S from C_11 and write output (no accumulation)
// ---------------------------------------------------------------------------
__global__ __launch_bounds__(256, 1) void pass_out_kernel(const float* __restrict__ feat,
                                                          float* __restrict__ out) {
    int b = blockIdx.x >> 5;
    int blk = blockIdx.x & 31;
    int t = threadIdx.x;

    float g[NK][NF], h[NK];
    #pragma unroll
    for (int k = 0; k < NK; k++) {
        h[k] = d_h[b * NK + k];
        #pragma unroll
        for (int f = 0; f < NF; f++) g[k][f] = d_g[(b * NK + k) * NF + f];
    }
    const float* base = feat + (size_t)b * NF * NPIX;
    #pragma unroll
    for (int it = 0; it < 8; it++) {
        int n4 = blk * 256 + t + it * 8192;
        float4 u[NF];
        #pragma unroll
        for (int f = 0; f < NF; f++)
            u[f] = ((const float4*)(base + (size_t)f * NPIX))[n4];
        float wv[NK][4];
        #pragma unroll
        for (int j = 0; j < 4; j++) {
            float x[NF];
            #pragma unroll
            for (int f = 0; f < NF; f++)
                x[f] = (j == 0) ? u[f].x : ((j == 1) ? u[f].y : ((j == 2) ? u[f].z : u[f].w));
            float l[NK];
            #pragma unroll
            for (int k = 0; k < NK; k++) {
                float a = h[k];
                #pragma unroll
                for (int f = 0; f < NF; f++) a = fmaf(x[f], g[k][f], a);
                l[k] = a;
            }
            float m = l[0];
            #pragma unroll
            for (int k = 1; k < NK; k++) m = fmaxf(m, l[k]);
            float p[NK]; float s = 0.f;
            #pragma unroll
            for (int k = 0; k < NK; k++) { p[k] = ex2f(l[k] - m); s += p[k]; }
            float r = rcpf(s);
            #pragma unroll
            for (int k = 0; k < NK; k++) wv[k][j] = p[k] * r;
        }
        #pragma unroll
        for (int k = 0; k < NK; k++) {
            float4 o4 = make_float4(wv[k][0], wv[k][1], wv[k][2], wv[k][3]);
            ((float4*)(out + (size_t)(b * NK + k) * NPIX))[n4] = o4;
        }
    }
}

extern "C" void kernel_launch(void* const* d_in, const int* in_sizes, int n_in,
                              void* d_out, int out_size) {
    const float* feat = (const float*)d_in[0];
    const int* idx = (const int*)d_in[1];
    float* out = (float*)d_out;

    stats_kernel<<<NB * NF * SPLIT, 256>>>(feat);
    init_kernel<<<1, 128>>>(feat, idx);
    for (int i = 0; i < NITERS - 1; i++) {
        pass_acc_kernel<<<NB * BPB, 256>>>(feat);
        update_kernel<<<1, 128>>>();
    }
    pass_out_kernel<<<NB * BPB, 256>>>(feat, out);
}

// round 2
// speedup vs baseline: 1.0110x; 1.0110x over previous
#include <cuda_runtime.h>

#define NB 16
#define NF 6
#define NPIX 262144
#define NK 8
#define NITERS 12
#define BPB 32          // blocks per batch in pass kernels
#define SPLIT 8         // blocks per (b,f) in stats kernel
#define NSLOT 56        // NK*(NF+1) partial-sum slots

// Scratch (static __device__ — no allocations allowed)
__device__ float d_statpart[NB * NF * SPLIT * 2];
__device__ float d_mean[NB * NF];
__device__ float d_sinv[NB * NF];
__device__ float d_g[NB * NK * NF];   // folded centroid weights: 2*alpha*s_f*c_kf
__device__ float d_h[NB * NK];        // folded centroid bias
__device__ float d_part[NB * BPB * NSLOT];

__device__ __forceinline__ float ex2f(float x) {
    float y; asm("ex2.approx.ftz.f32 %0, %1;" : "=f"(y) : "f"(x)); return y;
}
__device__ __forceinline__ float rcpf(float x) {
    float y; asm("rcp.approx.ftz.f32 %0, %1;" : "=f"(y) : "f"(x)); return y;
}

// ---------------------------------------------------------------------------
// Per-(b,f) sum / sumsq partials over pixels
// ---------------------------------------------------------------------------
__global__ __launch_bounds__(256) void stats_kernel(const float* __restrict__ feat) {
    int bf = blockIdx.x >> 3;     // / SPLIT
    int part = blockIdx.x & 7;    // % SPLIT
    const float4* p = ((const float4*)feat) + (size_t)bf * (NPIX / 4);
    int t = threadIdx.x;
    float s = 0.f, q = 0.f;
    #pragma unroll 8
    for (int i = 0; i < 32; i++) {
        float4 v = p[part * 8192 + i * 256 + t];
        s += (v.x + v.y) + (v.z + v.w);
        q = fmaf(v.x, v.x, q); q = fmaf(v.y, v.y, q);
        q = fmaf(v.z, v.z, q); q = fmaf(v.w, v.w, q);
    }
    #pragma unroll
    for (int o = 16; o; o >>= 1) {
        s += __shfl_xor_sync(0xffffffffu, s, o);
        q += __shfl_xor_sync(0xffffffffu, q, o);
    }
    __shared__ float sm[16];
    if ((t & 31) == 0) { sm[t >> 5] = s; sm[8 + (t >> 5)] = q; }
    __syncthreads();
    if (t == 0) {
        float S = 0.f, Q = 0.f;
        #pragma unroll
        for (int i = 0; i < 8; i++) { S += sm[i]; Q += sm[8 + i]; }
        d_statpart[(bf * SPLIT + part) * 2 + 0] = S;
        d_statpart[(bf * SPLIT + part) * 2 + 1] = Q;
    }
}

// ---------------------------------------------------------------------------
// Finalize mean/invstd; gather initial centroids; fold into (g, h)
// logit_k(pixel) = sum_f u_f * g_kf + h_k   (softmax shift-invariance used to
// drop the per-pixel x2/T term; log2e folded so exp is a single MUFU ex2)
// ---------------------------------------------------------------------------
__global__ void init_kernel(const float* __restrict__ feat, const int* __restrict__ idx) {
    int t = threadIdx.x;  // 128 = NB*NK
    if (t < NB * NF) {
        float S = 0.f, Q = 0.f;
        for (int i = 0; i < SPLIT; i++) {
            S += d_statpart[(t * SPLIT + i) * 2 + 0];
            Q += d_statpart[(t * SPLIT + i) * 2 + 1];
        }
        float mean = S * (1.f / (float)NPIX);
        float var = (Q - (float)NPIX * mean * mean) * (1.f / (float)(NPIX - 1));
        var = fmaxf(var, 0.f);
        float sd = sqrtf(var);
        d_mean[t] = mean;
        d_sinv[t] = 1.f / fmaxf(sd, 1e-6f);
    }
    __syncthreads();
    int b = t >> 3;
    int n = idx[t];
    const float alpha = 1.4426950408889634f / 0.15f;  // log2(e)/TEMP
    float c2 = 0.f;
    float g[NF];
    #pragma unroll
    for (int f = 0; f < NF; f++) {
        float u = feat[(size_t)(b * NF + f) * NPIX + n];
        float c = (u - d_mean[b * NF + f]) * d_sinv[b * NF + f];
        c2 = fmaf(c, c, c2);
        g[f] = 2.f * alpha * d_sinv[b * NF + f] * c;
    }
    float h = -alpha * c2;
    #pragma unroll
    for (int f = 0; f < NF; f++) {
        h -= d_mean[b * NF + f] * g[f];
        d_g[t * NF + f] = g[f];
    }
    d_h[t] = h;
}

// ---------------------------------------------------------------------------
// Main accumulation pass: softmax assignment + accumulate (W, A) partials
// ---------------------------------------------------------------------------
__global__ __launch_bounds__(256, 1) void pass_acc_kernel(const float* __restrict__ feat) {
    int b = blockIdx.x >> 5;   // / BPB
    int blk = blockIdx.x & 31; // % BPB
    int t = threadIdx.x;

    float g[NK][NF], h[NK];
    #pragma unroll
    for (int k = 0; k < NK; k++) {
        h[k] = d_h[b * NK + k];
        #pragma unroll
        for (int f = 0; f < NF; f++) g[k][f] = d_g[(b * NK + k) * NF + f];
    }
    float aW[NK];
    float aA[NK][NF];
    #pragma unroll
    for (int k = 0; k < NK; k++) {
        aW[k] = 0.f;
        #pragma unroll
        for (int f = 0; f < NF; f++) aA[k][f] = 0.f;
    }

    const float* base = feat + (size_t)b * NF * NPIX;
    #pragma unroll
    for (int it = 0; it < 8; it++) {
        int n4 = blk * 256 + t + it * 8192;
        float4 u[NF];
        #pragma unroll
        for (int f = 0; f < NF; f++)
            u[f] = ((const float4*)(base + (size_t)f * NPIX))[n4];
        #pragma unroll
        for (int j = 0; j < 4; j++) {
            float x[NF];
            #pragma unroll
            for (int f = 0; f < NF; f++)
                x[f] = (j == 0) ? u[f].x : ((j == 1) ? u[f].y : ((j == 2) ? u[f].z : u[f].w));
            float l[NK];
            #pragma unroll
            for (int k = 0; k < NK; k++) {
                float a = h[k];
                #pragma unroll
                for (int f = 0; f < NF; f++) a = fmaf(x[f], g[k][f], a);
                l[k] = a;
            }
            float m = l[0];
            #pragma unroll
            for (int k = 1; k < NK; k++) m = fmaxf(m, l[k]);
            float p[NK]; float s = 0.f;
            #pragma unroll
            for (int k = 0; k < NK; k++) { p[k] = ex2f(l[k] - m); s += p[k]; }
            float r = rcpf(s);
            float xr[NF];
            #pragma unroll
            for (int f = 0; f < NF; f++) xr[f] = x[f] * r;
            #pragma unroll
            for (int k = 0; k < NK; k++) {
                aW[k] = fmaf(p[k], r, aW[k]);
                #pragma unroll
                for (int f = 0; f < NF; f++) aA[k][f] = fmaf(p[k], xr[f], aA[k][f]);
            }
        }
    }

    // Deterministic block reduction: warp shfl -> smem per-warp -> fixed-order sum
    __shared__ float sm[8][NSLOT];
    int w = t >> 5, lane = t & 31;
    #pragma unroll
    for (int k = 0; k < NK; k++) {
        #pragma unroll
        for (int f = 0; f < NF; f++) {
            float v = aA[k][f];
            #pragma unroll
            for (int o = 16; o; o >>= 1) v += __shfl_xor_sync(0xffffffffu, v, o);
            if (lane == 0) sm[w][k * NF + f] = v;
        }
        float v = aW[k];
        #pragma unroll
        for (int o = 16; o; o >>= 1) v += __shfl_xor_sync(0xffffffffu, v, o);
        if (lane == 0) sm[w][48 + k] = v;
    }
    __syncthreads();
    if (t < NSLOT) {
        float v = 0.f;
        #pragma unroll
        for (int i = 0; i < 8; i++) v += sm[i][t];
        d_part[(size_t)(b * BPB + blk) * NSLOT + t] = v;
    }
}

// ---------------------------------------------------------------------------
// Centroid update in raw-u space, refold into (g, h); fixed reduction order
// ---------------------------------------------------------------------------
__global__ void update_kernel() {
    int t = threadIdx.x;  // 128 = NB*NK
    int b = t >> 3, k = t & 7;
    float W = 0.f;
    float A[NF] = {0.f, 0.f, 0.f, 0.f, 0.f, 0.f};
    for (int blk = 0; blk < BPB; blk++) {
        const float* pp = d_part + (size_t)(b * BPB + blk) * NSLOT;
        W += pp[48 + k];
        #pragma unroll
        for (int f = 0; f < NF; f++) A[f] += pp[k * NF + f];
    }
    float Wc = fmaxf(W, 1e-6f);
    float rW = 1.f / Wc;
    const float alpha = 1.4426950408889634f / 0.15f;
    float c2 = 0.f;
    float g[NF];
    #pragma unroll
    for (int f = 0; f < NF; f++) {
        // C_kf = s_f * (A_f - m_f*W) / clip(W, EPS)   (matches reference exactly)
        float c = d_sinv[b * NF + f] * (A[f] - d_mean[b * NF + f] * W) * rW;
        c2 = fmaf(c, c, c2);
        g[f] = 2.f * alpha * d_sinv[b * NF + f] * c;
    }
    float h = -alpha * c2;
    #pragma unroll
    for (int f = 0; f < NF; f++) {
        h -= d_mean[b * NF + f] * g[f];
        d_g[t * NF + f] = g[f];
    }
    d_h[t] = h;
}

// ---------------------------------------------------------------------------
// Final pass: compute S from C_11 and write output (no accumulation)
// ---------------------------------------------------------------------------
__global__ __launch_bounds__(256, 1) void pass_out_kernel(const float* __restrict__ feat,
                                                          float* __restrict__ out) {
    int b = blockIdx.x >> 5;
    int blk = blockIdx.x & 31;
    int t = threadIdx.x;

    float g[NK][NF], h[NK];
    #pragma unroll
    for (int k = 0; k < NK; k++) {
        h[k] = d_h[b * NK + k];
        #pragma unroll
        for (int f = 0; f < NF; f++) g[k][f] = d_g[(b * NK + k) * NF + f];
    }
    const float* base = feat + (size_t)b * NF * NPIX;
    #pragma unroll
    for (int it = 0; it < 8; it++) {
        int n4 = blk * 256 + t + it * 8192;
        float4 u[NF];
        #pragma unroll
        for (int f = 0; f < NF; f++)
            u[f] = ((const float4*)(base + (size_t)f * NPIX))[n4];
        float wv[NK][4];
        #pragma unroll
        for (int j = 0; j < 4; j++) {
            float x[NF];
            #pragma unroll
            for (int f = 0; f < NF; f++)
                x[f] = (j == 0) ? u[f].x : ((j == 1) ? u[f].y : ((j == 2) ? u[f].z : u[f].w));
            float l[NK];
            #pragma unroll
            for (int k = 0; k < NK; k++) {
                float a = h[k];
                #pragma unroll
                for (int f = 0; f < NF; f++) a = fmaf(x[f], g[k][f], a);
                l[k] = a;
            }
            float m = l[0];
            #pragma unroll
            for (int k = 1; k < NK; k++) m = fmaxf(m, l[k]);
            float p[NK]; float s = 0.f;
            #pragma unroll
            for (int k = 0; k < NK; k++) { p[k] = ex2f(l[k] - m); s += p[k]; }
            float r = rcpf(s);
            #pragma unroll
            for (int k = 0; k < NK; k++) wv[k][j] = p[k] * r;
        }
        #pragma unroll
        for (int k = 0; k < NK; k++) {
            float4 o4 = make_float4(wv[k][0], wv[k][1], wv[k][2], wv[k][3]);
            ((float4*)(out + (size_t)(b * NK + k) * NPIX))[n4] = o4;
        }
    }
}

extern "C" void kernel_launch(void* const* d_in, const int* in_sizes, int n_in,
                              void* d_out, int out_size) {
    const float* feat = (const float*)d_in[0];
    const int* idx = (const int*)d_in[1];
    float* out = (float*)d_out;

    stats_kernel<<<NB * NF * SPLIT, 256>>>(feat);
    init_kernel<<<1, 128>>>(feat, idx);
    for (int i = 0; i < NITERS - 1; i++) {
        pass_acc_kernel<<<NB * BPB, 256>>>(feat);
        update_kernel<<<1, 128>>>();
    }
    pass_out_kernel<<<NB * BPB, 256>>>(feat, out);
}